// round 9
// baseline (speedup 1.0000x reference)
#include <cuda_runtime.h>
#include <cuda.h>
#include <cstdint>

// ===========================================================================
// LinearToeplitz via FFT correlation, in-place DIF->DIT, 2 CTAs/SM.
// out[b,o] = sum_i x[b,i] * p[i + (O-1-o)] + bias[o],  B=8192, I=O=4096.
// corr = (1/N) * FFT( FFT(z) .* conj(P) ),  z = x_a + i*x_b,  P = FFT(p_pad).
// Radices [8,8,8,8,2]; the S=2 and S=1 stages (both directions) + pointwise
// are fused into ONE register phase using shfl.xor pair exchange.
// ===========================================================================

#define BATCH_SZ 8192
#define IFEAT    4096
#define OFEAT    4096
#define NFFT     8192
#define NTHREADS 512

__device__ __forceinline__ int PHYS(int i) { return i + (i >> 3); }
#define BUF_F2 9216
#define SMEM_TOTAL (BUF_F2 * 8)            // 73728 bytes -> 2 CTAs/SM

// ------------------------- global tables -------------------------
__device__ float2 g_tw[NFFT];   // e^{-2*pi*i*k/N}
__device__ float2 g_P[NFFT];    // conj(DIF(p_pad)) in DIF slot order

// ------------------------- complex helpers -------------------------
__device__ __forceinline__ float2 cmul(float2 a, float2 b) {
    return make_float2(a.x * b.x - a.y * b.y, a.x * b.y + a.y * b.x);
}
__device__ __forceinline__ float2 cadd(float2 a, float2 b) {
    return make_float2(a.x + b.x, a.y + b.y);
}
__device__ __forceinline__ float2 csub(float2 a, float2 b) {
    return make_float2(a.x - b.x, a.y - b.y);
}
__device__ __forceinline__ float2 cmni(float2 a) { return make_float2(a.y, -a.x); }
__device__ __forceinline__ float2 shflx1(float2 v) {
    return make_float2(__shfl_xor_sync(0xffffffffu, v.x, 1),
                       __shfl_xor_sync(0xffffffffu, v.y, 1));
}

// forward DFT-8 (w8 = e^{-2pi i/8})
__device__ __forceinline__ void dft8(float2 v[8]) {
    const float S = 0.70710678118654752440f;
    float2 t0 = cadd(v[0], v[4]), t1 = csub(v[0], v[4]);
    float2 t2 = cadd(v[2], v[6]), t3 = cmni(csub(v[2], v[6]));
    float2 t4 = cadd(v[1], v[5]), t5 = csub(v[1], v[5]);
    float2 t6 = cadd(v[3], v[7]), t7 = cmni(csub(v[3], v[7]));
    float2 e0 = cadd(t0, t2), e1 = cadd(t1, t3), e2 = csub(t0, t2), e3 = csub(t1, t3);
    float2 o0 = cadd(t4, t6), o1 = cadd(t5, t7), o2 = csub(t4, t6), o3 = csub(t5, t7);
    o1 = cmul(o1, make_float2(S, -S));
    o2 = cmni(o2);
    o3 = cmul(o3, make_float2(-S, -S));
    v[0] = cadd(e0, o0); v[4] = csub(e0, o0);
    v[1] = cadd(e1, o1); v[5] = csub(e1, o1);
    v[2] = cadd(e2, o2); v[6] = csub(e2, o2);
    v[3] = cadd(e3, o3); v[7] = csub(e3, o3);
}

// multiply v[1..7] by w^r, w = g_tw[idx] (idx may be 0 -> skip)
__device__ __forceinline__ void twmul(float2 v[8], int idx) {
    if (idx) {
        float2 w1 = g_tw[idx], w2 = g_tw[2 * idx], w4 = g_tw[4 * idx];
        float2 w3 = cmul(w1, w2), w5 = cmul(w1, w4);
        float2 w6 = cmul(w2, w4), w7 = cmul(w3, w4);
        v[1] = cmul(v[1], w1); v[2] = cmul(v[2], w2); v[3] = cmul(v[3], w3);
        v[4] = cmul(v[4], w4); v[5] = cmul(v[5], w5); v[6] = cmul(v[6], w6);
        v[7] = cmul(v[7], w7);
    }
}

// In-place radix-8 pass at span S. PRE=true: twiddle before dft (DIT);
// PRE=false: twiddle after dft (DIF).
template <int S, bool PRE>
__device__ __forceinline__ void pass8_ip(float2* a, int tid) {
    #pragma unroll 1
    for (int b = 0; b < 2; ++b) {
        int w = tid + b * NTHREADS;               // [0, 1024)
        int q = w & (S - 1);
        int base = ((w & ~(S - 1)) << 3) + q;     // (w/S)*8S + q
        int idx = q * (NFFT / (8 * S));
        float2 v[8];
        #pragma unroll
        for (int r = 0; r < 8; ++r) v[r] = a[PHYS(base + r * S)];
        if (PRE) twmul(v, idx);
        dft8(v);
        if (!PRE) twmul(v, idx);
        #pragma unroll
        for (int r = 0; r < 8; ++r) a[PHYS(base + r * S)] = v[r];
    }
}

// radix-2 at S=1 (no twiddle) — used by prep only
__device__ __forceinline__ void pass2_ip(float2* a, int tid) {
    #pragma unroll 1
    for (int s = 0; s < 8; ++s) {
        int m = tid + s * NTHREADS;
        int i0 = PHYS(2 * m), i1 = PHYS(2 * m + 1);
        float2 e0 = a[i0], e1 = a[i1];
        a[i0] = cadd(e0, e1);
        a[i1] = csub(e0, e1);
    }
}

// ------------------------- prep kernels -------------------------
__global__ void prep_tw_kernel() {
    int k = blockIdx.x * 256 + threadIdx.x;
    float s, c;
    sincospif(-(float)k / 4096.0f, &s, &c);
    g_tw[k] = make_float2(c, s);
}

// Run the SAME DIF on p_pad (one CTA), store conj in slot order. (unchanged)
__global__ void __launch_bounds__(NTHREADS, 2) prep_P_kernel(const float* __restrict__ p) {
    extern __shared__ __align__(16) float2 a[];
    const int tid = threadIdx.x;
    for (int i = tid; i < NFFT; i += NTHREADS) {
        float v = (i < NFFT - 1) ? __ldg(p + i) : 0.f;
        a[PHYS(i)] = make_float2(v, 0.f);
    }
    __syncthreads();
    pass8_ip<1024, false>(a, tid); __syncthreads();
    pass8_ip<128,  false>(a, tid); __syncthreads();
    pass8_ip<16,   false>(a, tid); __syncthreads();
    pass8_ip<2,    false>(a, tid); __syncthreads();
    pass2_ip(a, tid);              __syncthreads();
    for (int i = tid; i < NFFT; i += NTHREADS) {
        float2 v = a[PHYS(i)];
        g_P[i] = make_float2(v.x, -v.y);
    }
}

// ------------------------- main kernel -------------------------
__global__ void __launch_bounds__(NTHREADS, 2) fft_toeplitz_kernel(
    const float* __restrict__ x,
    const float* __restrict__ bias,
    float* __restrict__ out)
{
    extern __shared__ __align__(16) float2 a[];
    const int tid = threadIdx.x;
    const size_t b0 = (size_t)blockIdx.x * 2;
    const float* xa = x + b0 * IFEAT;
    const float* xb = xa + IFEAT;

    // ---- DIF pass S=1024 fused with global load (upper half = zero pad) ----
    #pragma unroll 1
    for (int b = 0; b < 2; ++b) {
        int w = tid + b * NTHREADS;
        float2 v[8];
        #pragma unroll
        for (int r = 0; r < 4; ++r)
            v[r] = make_float2(__ldg(xa + w + r * 1024), __ldg(xb + w + r * 1024));
        #pragma unroll
        for (int r = 4; r < 8; ++r) v[r] = make_float2(0.f, 0.f);
        dft8(v);
        twmul(v, w);
        #pragma unroll
        for (int r = 0; r < 8; ++r) a[PHYS(w + r * 1024)] = v[r];
    }
    __syncthreads();

    pass8_ip<128, false>(a, tid); __syncthreads();
    pass8_ip<16,  false>(a, tid); __syncthreads();

    // ---- FUSED register phase: r8@S2(DIF) + r2 + pointwise + r2 + r8@S2(DIT)
    // Thread pair (q = w&1, partner = lane^1) owns even/odd slots of one
    // 16-element block; the two radix-2 exchanges are shfl.xor(1).
    #pragma unroll 1
    for (int b = 0; b < 2; ++b) {
        int w = tid + b * NTHREADS;               // [0, 1024)
        int q    = w & 1;
        int base = ((w >> 1) << 4) + q;           // m16*16 + q
        int idx  = q * 512;                       // twiddle: w16 = g_tw[512]
        float2 v[8];
        #pragma unroll
        for (int r = 0; r < 8; ++r) v[r] = a[PHYS(base + 2 * r)];
        dft8(v);
        twmul(v, idx);                            // DIF r8@S2 twiddle (after)
        // r2 -> pointwise(.* g_P) -> r2, pairwise via shfl
        const float2* Pp = g_P + base;
        #pragma unroll
        for (int r = 0; r < 8; ++r) {
            float2 o = shflx1(v[r]);
            float2 f = q ? csub(o, v[r]) : cadd(v[r], o);
            f = cmul(f, __ldg(Pp + 2 * r));
            float2 o2 = shflx1(f);
            v[r] = q ? csub(o2, f) : cadd(f, o2);
        }
        twmul(v, idx);                            // DIT r8@S2 twiddle (before)
        dft8(v);
        #pragma unroll
        for (int r = 0; r < 8; ++r) a[PHYS(base + 2 * r)] = v[r];
    }
    __syncthreads();

    pass8_ip<16,  true>(a, tid); __syncthreads();
    pass8_ip<128, true>(a, tid); __syncthreads();

    // ---- DIT pass S=1024 fused with global store (keep j < 4096) ----
    const float inv = 1.0f / (float)NFFT;
    float* o0 = out + b0 * OFEAT;
    float* o1 = o0 + OFEAT;
    #pragma unroll 1
    for (int b = 0; b < 2; ++b) {
        int w = tid + b * NTHREADS;
        float2 v[8];
        #pragma unroll
        for (int r = 0; r < 8; ++r) v[r] = a[PHYS(w + r * 1024)];
        twmul(v, w);
        dft8(v);
        #pragma unroll
        for (int r = 0; r < 4; ++r) {
            int j = w + r * 1024;
            int o = OFEAT - 1 - j;
            float bb = __ldg(bias + o);
            o0[o] = v[r].x * inv + bb;
            o1[o] = v[r].y * inv + bb;
        }
    }
}

// ------------------------- host launch -------------------------
extern "C" void kernel_launch(void* const* d_in, const int* in_sizes, int n_in,
                              void* d_out, int out_size) {
    const float* x    = (const float*)d_in[0];
    const float* p    = (const float*)d_in[1];
    const float* bias = (const float*)d_in[2];
    float* out        = (float*)d_out;
    (void)in_sizes; (void)n_in; (void)out_size;

    cudaFuncSetAttribute(prep_P_kernel,
                         cudaFuncAttributeMaxDynamicSharedMemorySize, SMEM_TOTAL);
    cudaFuncSetAttribute(fft_toeplitz_kernel,
                         cudaFuncAttributeMaxDynamicSharedMemorySize, SMEM_TOTAL);

    prep_tw_kernel<<<NFFT / 256, 256>>>();
    prep_P_kernel<<<1, NTHREADS, SMEM_TOTAL>>>(p);
    fft_toeplitz_kernel<<<BATCH_SZ / 2, NTHREADS, SMEM_TOTAL>>>(x, bias, out);
}

// round 10
// speedup vs baseline: 1.4192x; 1.4192x over previous
#include <cuda_runtime.h>
#include <cuda.h>
#include <cstdint>

// ===========================================================================
// LinearToeplitz via FFT correlation, in-place DIF->DIT, 2 CTAs/SM.
// out[b,o] = sum_i x[b,i] * p[i + (O-1-o)] + bias[o],  B=8192, I=O=4096.
// corr = (1/N) * FFT( FFT(z) .* conj(P) ),  z = x_a + i*x_b,  P = FFT(p_pad).
// R10: R7 phase structure (it beat the shfl-fused R9), but twmul uses ONE
// twiddle load + register powers (w2=w1^2, ...) -> 3x fewer LDGs and the
// hot twiddle footprint drops 64KB -> <=8KB (L1-resident).
// ===========================================================================

#define BATCH_SZ 8192
#define IFEAT    4096
#define OFEAT    4096
#define NFFT     8192
#define NTHREADS 512

__device__ __forceinline__ int PHYS(int i) { return i + (i >> 3); }
#define BUF_F2 9216
#define SMEM_TOTAL (BUF_F2 * 8)            // 73728 bytes -> 2 CTAs/SM

// ------------------------- global tables -------------------------
__device__ float2 g_tw[NFFT];   // e^{-2*pi*i*k/N}
__device__ float2 g_P[NFFT];    // conj(DIF(p_pad)) in DIF slot order

// ------------------------- complex helpers -------------------------
__device__ __forceinline__ float2 cmul(float2 a, float2 b) {
    return make_float2(a.x * b.x - a.y * b.y, a.x * b.y + a.y * b.x);
}
__device__ __forceinline__ float2 cadd(float2 a, float2 b) {
    return make_float2(a.x + b.x, a.y + b.y);
}
__device__ __forceinline__ float2 csub(float2 a, float2 b) {
    return make_float2(a.x - b.x, a.y - b.y);
}
__device__ __forceinline__ float2 cmni(float2 a) { return make_float2(a.y, -a.x); }

// forward DFT-8 (w8 = e^{-2pi i/8})
__device__ __forceinline__ void dft8(float2 v[8]) {
    const float S = 0.70710678118654752440f;
    float2 t0 = cadd(v[0], v[4]), t1 = csub(v[0], v[4]);
    float2 t2 = cadd(v[2], v[6]), t3 = cmni(csub(v[2], v[6]));
    float2 t4 = cadd(v[1], v[5]), t5 = csub(v[1], v[5]);
    float2 t6 = cadd(v[3], v[7]), t7 = cmni(csub(v[3], v[7]));
    float2 e0 = cadd(t0, t2), e1 = cadd(t1, t3), e2 = csub(t0, t2), e3 = csub(t1, t3);
    float2 o0 = cadd(t4, t6), o1 = cadd(t5, t7), o2 = csub(t4, t6), o3 = csub(t5, t7);
    o1 = cmul(o1, make_float2(S, -S));
    o2 = cmni(o2);
    o3 = cmul(o3, make_float2(-S, -S));
    v[0] = cadd(e0, o0); v[4] = csub(e0, o0);
    v[1] = cadd(e1, o1); v[5] = csub(e1, o1);
    v[2] = cadd(e2, o2); v[6] = csub(e2, o2);
    v[3] = cadd(e3, o3); v[7] = csub(e3, o3);
}

// multiply v[1..7] by w^r from ONE table load: w^r built by register powers.
__device__ __forceinline__ void twmul(float2 v[8], int idx) {
    if (idx) {
        float2 w1 = g_tw[idx];
        float2 w2 = cmul(w1, w1);
        float2 w3 = cmul(w1, w2);
        float2 w4 = cmul(w2, w2);
        float2 w5 = cmul(w1, w4);
        float2 w6 = cmul(w2, w4);
        float2 w7 = cmul(w3, w4);
        v[1] = cmul(v[1], w1); v[2] = cmul(v[2], w2); v[3] = cmul(v[3], w3);
        v[4] = cmul(v[4], w4); v[5] = cmul(v[5], w5); v[6] = cmul(v[6], w6);
        v[7] = cmul(v[7], w7);
    }
}

// In-place radix-8 pass at span S. PRE=true: twiddle before dft (DIT);
// PRE=false: twiddle after dft (DIF).
template <int S, bool PRE>
__device__ __forceinline__ void pass8_ip(float2* a, int tid) {
    #pragma unroll 1
    for (int b = 0; b < 2; ++b) {
        int w = tid + b * NTHREADS;               // [0, 1024)
        int q = w & (S - 1);
        int base = ((w & ~(S - 1)) << 3) + q;     // (w/S)*8S + q
        int idx = q * (NFFT / (8 * S));
        float2 v[8];
        #pragma unroll
        for (int r = 0; r < 8; ++r) v[r] = a[PHYS(base + r * S)];
        if (PRE) twmul(v, idx);
        dft8(v);
        if (!PRE) twmul(v, idx);
        #pragma unroll
        for (int r = 0; r < 8; ++r) a[PHYS(base + r * S)] = v[r];
    }
}

// radix-2 at S=1 (no twiddle) — used by prep only
__device__ __forceinline__ void pass2_ip(float2* a, int tid) {
    #pragma unroll 1
    for (int s = 0; s < 8; ++s) {
        int m = tid + s * NTHREADS;
        int i0 = PHYS(2 * m), i1 = PHYS(2 * m + 1);
        float2 e0 = a[i0], e1 = a[i1];
        a[i0] = cadd(e0, e1);
        a[i1] = csub(e0, e1);
    }
}

// ------------------------- prep kernel -------------------------
// Single CTA: (1) fill g_tw, (2) run the SAME DIF on p_pad, (3) store conj(P)
// in DIF slot order. g_tw reads below hit this CTA's own prior global writes
// (same SM, after __syncthreads) — coherent.
__global__ void __launch_bounds__(NTHREADS, 2) prep_P_kernel(const float* __restrict__ p) {
    extern __shared__ __align__(16) float2 a[];
    const int tid = threadIdx.x;

    for (int k = tid; k < NFFT; k += NTHREADS) {
        float s, c;
        sincospif(-(float)k / 4096.0f, &s, &c);   // angle = -2*pi*k/8192
        g_tw[k] = make_float2(c, s);
    }
    __threadfence();
    __syncthreads();

    for (int i = tid; i < NFFT; i += NTHREADS) {
        float v = (i < NFFT - 1) ? __ldg(p + i) : 0.f;
        a[PHYS(i)] = make_float2(v, 0.f);
    }
    __syncthreads();
    pass8_ip<1024, false>(a, tid); __syncthreads();
    pass8_ip<128,  false>(a, tid); __syncthreads();
    pass8_ip<16,   false>(a, tid); __syncthreads();
    pass8_ip<2,    false>(a, tid); __syncthreads();
    pass2_ip(a, tid);              __syncthreads();
    for (int i = tid; i < NFFT; i += NTHREADS) {
        float2 v = a[PHYS(i)];
        g_P[i] = make_float2(v.x, -v.y);
    }
}

// ------------------------- main kernel -------------------------
__global__ void __launch_bounds__(NTHREADS, 2) fft_toeplitz_kernel(
    const float* __restrict__ x,
    const float* __restrict__ bias,
    float* __restrict__ out)
{
    extern __shared__ __align__(16) float2 a[];
    const int tid = threadIdx.x;
    const size_t b0 = (size_t)blockIdx.x * 2;
    const float* xa = x + b0 * IFEAT;
    const float* xb = xa + IFEAT;

    // ---- DIF pass S=1024 fused with global load (upper half = zero pad) ----
    #pragma unroll 1
    for (int b = 0; b < 2; ++b) {
        int w = tid + b * NTHREADS;
        float2 v[8];
        #pragma unroll
        for (int r = 0; r < 4; ++r)
            v[r] = make_float2(__ldg(xa + w + r * 1024), __ldg(xb + w + r * 1024));
        #pragma unroll
        for (int r = 4; r < 8; ++r) v[r] = make_float2(0.f, 0.f);
        dft8(v);
        twmul(v, w);
        #pragma unroll
        for (int r = 0; r < 8; ++r) a[PHYS(w + r * 1024)] = v[r];
    }
    __syncthreads();

    pass8_ip<128, false>(a, tid); __syncthreads();
    pass8_ip<16,  false>(a, tid); __syncthreads();
    pass8_ip<2,   false>(a, tid); __syncthreads();

    // ---- fused: DIF radix-2 + pointwise (.* g_P) + DIT radix-2 ----
    #pragma unroll 1
    for (int s = 0; s < 8; ++s) {
        int m = tid + s * NTHREADS;
        int i0 = PHYS(2 * m), i1 = PHYS(2 * m + 1);
        float2 e0 = a[i0], e1 = a[i1];
        float2 f0 = cadd(e0, e1), f1 = csub(e0, e1);
        float4 pp = *reinterpret_cast<const float4*>(g_P + 2 * m);
        f0 = cmul(f0, make_float2(pp.x, pp.y));
        f1 = cmul(f1, make_float2(pp.z, pp.w));
        a[i0] = cadd(f0, f1);
        a[i1] = csub(f0, f1);
    }
    __syncthreads();

    pass8_ip<2,   true>(a, tid); __syncthreads();
    pass8_ip<16,  true>(a, tid); __syncthreads();
    pass8_ip<128, true>(a, tid); __syncthreads();

    // ---- DIT pass S=1024 fused with global store (keep j < 4096) ----
    const float inv = 1.0f / (float)NFFT;
    float* o0 = out + b0 * OFEAT;
    float* o1 = o0 + OFEAT;
    #pragma unroll 1
    for (int b = 0; b < 2; ++b) {
        int w = tid + b * NTHREADS;
        float2 v[8];
        #pragma unroll
        for (int r = 0; r < 8; ++r) v[r] = a[PHYS(w + r * 1024)];
        twmul(v, w);
        dft8(v);
        #pragma unroll
        for (int r = 0; r < 4; ++r) {
            int j = w + r * 1024;
            int o = OFEAT - 1 - j;
            float bb = __ldg(bias + o);
            o0[o] = v[r].x * inv + bb;
            o1[o] = v[r].y * inv + bb;
        }
    }
}

// ------------------------- host launch -------------------------
extern "C" void kernel_launch(void* const* d_in, const int* in_sizes, int n_in,
                              void* d_out, int out_size) {
    const float* x    = (const float*)d_in[0];
    const float* p    = (const float*)d_in[1];
    const float* bias = (const float*)d_in[2];
    float* out        = (float*)d_out;
    (void)in_sizes; (void)n_in; (void)out_size;

    cudaFuncSetAttribute(prep_P_kernel,
                         cudaFuncAttributeMaxDynamicSharedMemorySize, SMEM_TOTAL);
    cudaFuncSetAttribute(fft_toeplitz_kernel,
                         cudaFuncAttributeMaxDynamicSharedMemorySize, SMEM_TOTAL);

    prep_P_kernel<<<1, NTHREADS, SMEM_TOTAL>>>(p);
    fft_toeplitz_kernel<<<BATCH_SZ / 2, NTHREADS, SMEM_TOTAL>>>(x, bias, out);
}

// round 12
// speedup vs baseline: 1.7373x; 1.2241x over previous
#include <cuda_runtime.h>
#include <cuda.h>
#include <cstdint>

// ===========================================================================
// LinearToeplitz via FFT correlation, in-place DIF->DIT, 2 CTAs/SM.
// out[b,o] = sum_i x[b,i] * p[i + (O-1-o)] + bias[o],  B=8192, I=O=4096.
// corr = (1/N) * FFT( FFT(z) .* conj(P) ),  z = x_a + i*x_b,  P = FFT(p_pad).
// R11: pad-by-16 smem layout (PHYS16) + lane-remapped S=2 passes ->
//      all smem passes bank-conflict-free (L1 was 86.7% = the wall in R10).
// ===========================================================================

#define BATCH_SZ 8192
#define IFEAT    4096
#define OFEAT    4096
#define NFFT     8192
#define NTHREADS 512

__device__ __forceinline__ int PHYS(int i) { return i + (i >> 4); }
#define BUF_F2 8704                        // PHYS(8191)=8702 < 8704
#define SMEM_TOTAL (BUF_F2 * 8)            // 69632 bytes -> 2 CTAs/SM

// ------------------------- global tables -------------------------
__device__ float2 g_tw[NFFT];   // e^{-2*pi*i*k/N}
__device__ float2 g_P[NFFT];    // conj(DIF(p_pad)) in DIF slot order

// ------------------------- complex helpers -------------------------
__device__ __forceinline__ float2 cmul(float2 a, float2 b) {
    return make_float2(a.x * b.x - a.y * b.y, a.x * b.y + a.y * b.x);
}
__device__ __forceinline__ float2 cadd(float2 a, float2 b) {
    return make_float2(a.x + b.x, a.y + b.y);
}
__device__ __forceinline__ float2 csub(float2 a, float2 b) {
    return make_float2(a.x - b.x, a.y - b.y);
}
__device__ __forceinline__ float2 cmni(float2 a) { return make_float2(a.y, -a.x); }

// forward DFT-8 (w8 = e^{-2pi i/8})
__device__ __forceinline__ void dft8(float2 v[8]) {
    const float S = 0.70710678118654752440f;
    float2 t0 = cadd(v[0], v[4]), t1 = csub(v[0], v[4]);
    float2 t2 = cadd(v[2], v[6]), t3 = cmni(csub(v[2], v[6]));
    float2 t4 = cadd(v[1], v[5]), t5 = csub(v[1], v[5]);
    float2 t6 = cadd(v[3], v[7]), t7 = cmni(csub(v[3], v[7]));
    float2 e0 = cadd(t0, t2), e1 = cadd(t1, t3), e2 = csub(t0, t2), e3 = csub(t1, t3);
    float2 o0 = cadd(t4, t6), o1 = cadd(t5, t7), o2 = csub(t4, t6), o3 = csub(t5, t7);
    o1 = cmul(o1, make_float2(S, -S));
    o2 = cmni(o2);
    o3 = cmul(o3, make_float2(-S, -S));
    v[0] = cadd(e0, o0); v[4] = csub(e0, o0);
    v[1] = cadd(e1, o1); v[5] = csub(e1, o1);
    v[2] = cadd(e2, o2); v[6] = csub(e2, o2);
    v[3] = cadd(e3, o3); v[7] = csub(e3, o3);
}

// multiply v[1..7] by w^r from ONE table load (register powers).
__device__ __forceinline__ void twmul(float2 v[8], int idx) {
    if (idx) {
        float2 w1 = g_tw[idx];
        float2 w2 = cmul(w1, w1);
        float2 w3 = cmul(w1, w2);
        float2 w4 = cmul(w2, w2);
        float2 w5 = cmul(w1, w4);
        float2 w6 = cmul(w2, w4);
        float2 w7 = cmul(w3, w4);
        v[1] = cmul(v[1], w1); v[2] = cmul(v[2], w2); v[3] = cmul(v[3], w3);
        v[4] = cmul(v[4], w4); v[5] = cmul(v[5], w5); v[6] = cmul(v[6], w6);
        v[7] = cmul(v[7], w7);
    }
}

// In-place radix-8 pass at span S (S >= 16 here). PRE: twiddle before dft.
template <int S, bool PRE>
__device__ __forceinline__ void pass8_ip(float2* a, int tid) {
    #pragma unroll 1
    for (int b = 0; b < 2; ++b) {
        int w = tid + b * NTHREADS;               // [0, 1024)
        int q = w & (S - 1);
        int base = ((w & ~(S - 1)) << 3) + q;     // (w/S)*8S + q
        int idx = q * (NFFT / (8 * S));
        float2 v[8];
        #pragma unroll
        for (int r = 0; r < 8; ++r) v[r] = a[PHYS(base + r * S)];
        if (PRE) twmul(v, idx);
        dft8(v);
        if (!PRE) twmul(v, idx);
        #pragma unroll
        for (int r = 0; r < 8; ++r) a[PHYS(base + r * S)] = v[r];
    }
}

// In-place radix-8 pass at S=2, lane-remapped: q = (w>>4)&1 so each 16-lane
// phase covers 16 consecutive blocks at fixed q -> conflict-free under PHYS16.
template <bool PRE>
__device__ __forceinline__ void pass8_s2(float2* a, int tid) {
    #pragma unroll 1
    for (int b = 0; b < 2; ++b) {
        int w = tid + b * NTHREADS;
        int q   = (w >> 4) & 1;
        int blk = (w & 15) | ((w >> 5) << 4);     // [0, 512)
        int base = blk * 16 + q;
        int idx  = q * 512;
        float2 v[8];
        #pragma unroll
        for (int r = 0; r < 8; ++r) v[r] = a[PHYS(base + 2 * r)];
        if (PRE) twmul(v, idx);
        dft8(v);
        if (!PRE) twmul(v, idx);
        #pragma unroll
        for (int r = 0; r < 8; ++r) a[PHYS(base + 2 * r)] = v[r];
    }
}

// radix-2 at S=1 (no twiddle) — used by prep only
__device__ __forceinline__ void pass2_ip(float2* a, int tid) {
    #pragma unroll 1
    for (int s = 0; s < 8; ++s) {
        int m = tid + s * NTHREADS;
        int i0 = PHYS(2 * m), i1 = PHYS(2 * m + 1);
        float2 e0 = a[i0], e1 = a[i1];
        a[i0] = cadd(e0, e1);
        a[i1] = csub(e0, e1);
    }
}

// ------------------------- prep kernel -------------------------
__global__ void __launch_bounds__(NTHREADS, 2) prep_P_kernel(const float* __restrict__ p) {
    extern __shared__ __align__(16) float2 a[];
    const int tid = threadIdx.x;

    for (int k = tid; k < NFFT; k += NTHREADS) {
        float s, c;
        sincospif(-(float)k / 4096.0f, &s, &c);
        g_tw[k] = make_float2(c, s);
    }
    __threadfence();
    __syncthreads();

    for (int i = tid; i < NFFT; i += NTHREADS) {
        float v = (i < NFFT - 1) ? __ldg(p + i) : 0.f;
        a[PHYS(i)] = make_float2(v, 0.f);
    }
    __syncthreads();
    pass8_ip<1024, false>(a, tid); __syncthreads();
    pass8_ip<128,  false>(a, tid); __syncthreads();
    pass8_ip<16,   false>(a, tid); __syncthreads();
    pass8_s2<false>(a, tid);       __syncthreads();
    pass2_ip(a, tid);              __syncthreads();
    for (int i = tid; i < NFFT; i += NTHREADS) {
        float2 v = a[PHYS(i)];
        g_P[i] = make_float2(v.x, -v.y);
    }
}

// ------------------------- main kernel -------------------------
__global__ void __launch_bounds__(NTHREADS, 2) fft_toeplitz_kernel(
    const float* __restrict__ x,
    const float* __restrict__ bias,
    float* __restrict__ out)
{
    extern __shared__ __align__(16) float2 a[];
    const int tid = threadIdx.x;
    const size_t b0 = (size_t)blockIdx.x * 2;
    const float* xa = x + b0 * IFEAT;
    const float* xb = xa + IFEAT;

    // ---- DIF pass S=1024 fused with global load (upper half = zero pad) ----
    #pragma unroll 1
    for (int b = 0; b < 2; ++b) {
        int w = tid + b * NTHREADS;
        float2 v[8];
        #pragma unroll
        for (int r = 0; r < 4; ++r)
            v[r] = make_float2(__ldg(xa + w + r * 1024), __ldg(xb + w + r * 1024));
        #pragma unroll
        for (int r = 4; r < 8; ++r) v[r] = make_float2(0.f, 0.f);
        dft8(v);
        twmul(v, w);
        #pragma unroll
        for (int r = 0; r < 8; ++r) a[PHYS(w + r * 1024)] = v[r];
    }
    __syncthreads();

    pass8_ip<128, false>(a, tid); __syncthreads();
    pass8_ip<16,  false>(a, tid); __syncthreads();
    pass8_s2<false>(a, tid);      __syncthreads();

    // ---- fused: DIF radix-2 + pointwise (.* g_P) + DIT radix-2 ----
    #pragma unroll 1
    for (int s = 0; s < 8; ++s) {
        int m = tid + s * NTHREADS;
        int i0 = PHYS(2 * m), i1 = PHYS(2 * m + 1);
        float2 e0 = a[i0], e1 = a[i1];
        float2 f0 = cadd(e0, e1), f1 = csub(e0, e1);
        float4 pp = *reinterpret_cast<const float4*>(g_P + 2 * m);
        f0 = cmul(f0, make_float2(pp.x, pp.y));
        f1 = cmul(f1, make_float2(pp.z, pp.w));
        a[i0] = cadd(f0, f1);
        a[i1] = csub(f0, f1);
    }
    __syncthreads();

    pass8_s2<true>(a, tid);      __syncthreads();
    pass8_ip<16,  true>(a, tid); __syncthreads();
    pass8_ip<128, true>(a, tid); __syncthreads();

    // ---- DIT pass S=1024 fused with global store (keep j < 4096) ----
    const float inv = 1.0f / (float)NFFT;
    float* o0 = out + b0 * OFEAT;
    float* o1 = o0 + OFEAT;
    #pragma unroll 1
    for (int b = 0; b < 2; ++b) {
        int w = tid + b * NTHREADS;
        float2 v[8];
        #pragma unroll
        for (int r = 0; r < 8; ++r) v[r] = a[PHYS(w + r * 1024)];
        twmul(v, w);
        dft8(v);
        #pragma unroll
        for (int r = 0; r < 4; ++r) {
            int j = w + r * 1024;
            int o = OFEAT - 1 - j;
            float bb = __ldg(bias + o);
            o0[o] = v[r].x * inv + bb;
            o1[o] = v[r].y * inv + bb;
        }
    }
}

// ------------------------- host launch -------------------------
extern "C" void kernel_launch(void* const* d_in, const int* in_sizes, int n_in,
                              void* d_out, int out_size) {
    const float* x    = (const float*)d_in[0];
    const float* p    = (const float*)d_in[1];
    const float* bias = (const float*)d_in[2];
    float* out        = (float*)d_out;
    (void)in_sizes; (void)n_in; (void)out_size;

    cudaFuncSetAttribute(prep_P_kernel,
                         cudaFuncAttributeMaxDynamicSharedMemorySize, SMEM_TOTAL);
    cudaFuncSetAttribute(fft_toeplitz_kernel,
                         cudaFuncAttributeMaxDynamicSharedMemorySize, SMEM_TOTAL);

    prep_P_kernel<<<1, NTHREADS, SMEM_TOTAL>>>(p);
    fft_toeplitz_kernel<<<BATCH_SZ / 2, NTHREADS, SMEM_TOTAL>>>(x, bias, out);
}

// round 13
// speedup vs baseline: 1.9257x; 1.1084x over previous
#include <cuda_runtime.h>
#include <cuda.h>
#include <cstdint>

// ===========================================================================
// LinearToeplitz via FFT correlation, in-place DIF->DIT, 2 CTAs/SM.
// out[b,o] = sum_i x[b,i] * p[i + (O-1-o)] + bias[o],  B=8192, I=O=4096.
// corr = (1/N) * FFT( FFT(z) .* conj(P) ),  z = x_a + i*x_b,  P = FFT(p_pad).
// R13: radix-16 network [16,16,16,2] -> 7 smem phases (was 9 with radix-8).
//      Pad-16 layout; all passes bank-conflict-free (incl. S=2 naturally).
// ===========================================================================

#define BATCH_SZ 8192
#define IFEAT    4096
#define OFEAT    4096
#define NFFT     8192
#define NTHREADS 512

__device__ __forceinline__ int PHYS(int i) { return i + (i >> 4); }
#define BUF_F2 8704
#define SMEM_TOTAL (BUF_F2 * 8)            // 69632 bytes -> 2 CTAs/SM

// ------------------------- global tables -------------------------
__device__ float2 g_tw[NFFT];   // e^{-2*pi*i*k/N}
__device__ float2 g_P[NFFT];    // conj(DIF(p_pad)) in DIF slot order

// ------------------------- complex helpers -------------------------
__device__ __forceinline__ float2 cmul(float2 a, float2 b) {
    return make_float2(a.x * b.x - a.y * b.y, a.x * b.y + a.y * b.x);
}
__device__ __forceinline__ float2 cadd(float2 a, float2 b) {
    return make_float2(a.x + b.x, a.y + b.y);
}
__device__ __forceinline__ float2 csub(float2 a, float2 b) {
    return make_float2(a.x - b.x, a.y - b.y);
}
__device__ __forceinline__ float2 cmni(float2 a) { return make_float2(a.y, -a.x); }

// forward DFT-8 (w8 = e^{-2pi i/8})
__device__ __forceinline__ void dft8(float2 v[8]) {
    const float S = 0.70710678118654752440f;
    float2 t0 = cadd(v[0], v[4]), t1 = csub(v[0], v[4]);
    float2 t2 = cadd(v[2], v[6]), t3 = cmni(csub(v[2], v[6]));
    float2 t4 = cadd(v[1], v[5]), t5 = csub(v[1], v[5]);
    float2 t6 = cadd(v[3], v[7]), t7 = cmni(csub(v[3], v[7]));
    float2 e0 = cadd(t0, t2), e1 = cadd(t1, t3), e2 = csub(t0, t2), e3 = csub(t1, t3);
    float2 o0 = cadd(t4, t6), o1 = cadd(t5, t7), o2 = csub(t4, t6), o3 = csub(t5, t7);
    o1 = cmul(o1, make_float2(S, -S));
    o2 = cmni(o2);
    o3 = cmul(o3, make_float2(-S, -S));
    v[0] = cadd(e0, o0); v[4] = csub(e0, o0);
    v[1] = cadd(e1, o1); v[5] = csub(e1, o1);
    v[2] = cadd(e2, o2); v[6] = csub(e2, o2);
    v[3] = cadd(e3, o3); v[7] = csub(e3, o3);
}

// forward DFT-16, natural in/out: split even/odd -> dft8 x2 -> combine.
__device__ __forceinline__ void dft16(float2 v[16]) {
    const float C1 = 0.92387953251128675613f;   // cos(pi/8)
    const float S1 = 0.38268343236508977173f;   // sin(pi/8)
    const float R  = 0.70710678118654752440f;
    float2 e[8], o[8];
    #pragma unroll
    for (int r = 0; r < 8; ++r) { e[r] = v[2 * r]; o[r] = v[2 * r + 1]; }
    dft8(e);
    dft8(o);
    o[1] = cmul(o[1], make_float2( C1, -S1));
    o[2] = cmul(o[2], make_float2(  R,  -R));
    o[3] = cmul(o[3], make_float2( S1, -C1));
    o[4] = cmni(o[4]);
    o[5] = cmul(o[5], make_float2(-S1, -C1));
    o[6] = cmul(o[6], make_float2( -R,  -R));
    o[7] = cmul(o[7], make_float2(-C1, -S1));
    #pragma unroll
    for (int k = 0; k < 8; ++k) {
        v[k]     = cadd(e[k], o[k]);
        v[k + 8] = csub(e[k], o[k]);
    }
}

// multiply v[1..15] by w^r from ONE table load (tree-built powers, depth 4).
__device__ __forceinline__ void twmul16(float2 v[16], int idx) {
    if (idx) {
        float2 w1 = g_tw[idx];
        float2 w2 = cmul(w1, w1);
        float2 w4 = cmul(w2, w2);
        float2 w8 = cmul(w4, w4);
        float2 w3 = cmul(w1, w2);
        float2 w5 = cmul(w1, w4);
        float2 w6 = cmul(w2, w4);
        float2 w7 = cmul(w3, w4);
        v[1]  = cmul(v[1],  w1);
        v[2]  = cmul(v[2],  w2);
        v[3]  = cmul(v[3],  w3);
        v[4]  = cmul(v[4],  w4);
        v[5]  = cmul(v[5],  w5);
        v[6]  = cmul(v[6],  w6);
        v[7]  = cmul(v[7],  w7);
        v[8]  = cmul(v[8],  w8);
        v[9]  = cmul(v[9],  cmul(w1, w8));
        v[10] = cmul(v[10], cmul(w2, w8));
        v[11] = cmul(v[11], cmul(w3, w8));
        v[12] = cmul(v[12], cmul(w4, w8));
        v[13] = cmul(v[13], cmul(w5, w8));
        v[14] = cmul(v[14], cmul(w6, w8));
        v[15] = cmul(v[15], cmul(w7, w8));
    }
}

// In-place radix-16 pass at span S. 512 butterflies == 512 threads (w = tid).
// PRE=true: twiddle before dft (DIT); PRE=false: twiddle after (DIF).
template <int S, bool PRE>
__device__ __forceinline__ void pass16_ip(float2* a, int w) {
    int q = w & (S - 1);
    int base = ((w & ~(S - 1)) << 4) + q;         // (w/S)*16S + q
    int idx = q * (NFFT / (16 * S));
    float2 v[16];
    #pragma unroll
    for (int r = 0; r < 16; ++r) v[r] = a[PHYS(base + r * S)];
    if (PRE) twmul16(v, idx);
    dft16(v);
    if (!PRE) twmul16(v, idx);
    #pragma unroll
    for (int r = 0; r < 16; ++r) a[PHYS(base + r * S)] = v[r];
}

// radix-2 at S=1 (no twiddle) — prep only
__device__ __forceinline__ void pass2_ip(float2* a, int tid) {
    #pragma unroll 1
    for (int s = 0; s < 8; ++s) {
        int m = tid + s * NTHREADS;
        int i0 = PHYS(2 * m), i1 = PHYS(2 * m + 1);
        float2 e0 = a[i0], e1 = a[i1];
        a[i0] = cadd(e0, e1);
        a[i1] = csub(e0, e1);
    }
}

// ------------------------- prep kernel -------------------------
__global__ void __launch_bounds__(NTHREADS, 2) prep_P_kernel(const float* __restrict__ p) {
    extern __shared__ __align__(16) float2 a[];
    const int tid = threadIdx.x;

    for (int k = tid; k < NFFT; k += NTHREADS) {
        float s, c;
        sincospif(-(float)k / 4096.0f, &s, &c);
        g_tw[k] = make_float2(c, s);
    }
    __threadfence();
    __syncthreads();

    for (int i = tid; i < NFFT; i += NTHREADS) {
        float v = (i < NFFT - 1) ? __ldg(p + i) : 0.f;
        a[PHYS(i)] = make_float2(v, 0.f);
    }
    __syncthreads();
    pass16_ip<512, false>(a, tid); __syncthreads();
    pass16_ip<32,  false>(a, tid); __syncthreads();
    pass16_ip<2,   false>(a, tid); __syncthreads();
    pass2_ip(a, tid);              __syncthreads();
    for (int i = tid; i < NFFT; i += NTHREADS) {
        float2 v = a[PHYS(i)];
        g_P[i] = make_float2(v.x, -v.y);
    }
}

// ------------------------- main kernel -------------------------
__global__ void __launch_bounds__(NTHREADS, 2) fft_toeplitz_kernel(
    const float* __restrict__ x,
    const float* __restrict__ bias,
    float* __restrict__ out)
{
    extern __shared__ __align__(16) float2 a[];
    const int tid = threadIdx.x;
    const size_t b0 = (size_t)blockIdx.x * 2;
    const float* xa = x + b0 * IFEAT;
    const float* xb = xa + IFEAT;

    // ---- DIF r16 @ S=512 fused with global load (r>=8 -> zero pad) ----
    {
        int j = tid;                               // q = j, base = j, idx = j
        float2 v[16];
        #pragma unroll
        for (int r = 0; r < 8; ++r)
            v[r] = make_float2(__ldg(xa + j + r * 512), __ldg(xb + j + r * 512));
        #pragma unroll
        for (int r = 8; r < 16; ++r) v[r] = make_float2(0.f, 0.f);
        dft16(v);
        twmul16(v, j);
        #pragma unroll
        for (int r = 0; r < 16; ++r) a[PHYS(j + r * 512)] = v[r];
    }
    __syncthreads();

    pass16_ip<32, false>(a, tid); __syncthreads();
    pass16_ip<2,  false>(a, tid); __syncthreads();

    // ---- fused: DIF radix-2 + pointwise (.* g_P) + DIT radix-2 ----
    #pragma unroll 1
    for (int s = 0; s < 8; ++s) {
        int m = tid + s * NTHREADS;
        int i0 = PHYS(2 * m), i1 = PHYS(2 * m + 1);
        float2 e0 = a[i0], e1 = a[i1];
        float2 f0 = cadd(e0, e1), f1 = csub(e0, e1);
        float4 pp = *reinterpret_cast<const float4*>(g_P + 2 * m);
        f0 = cmul(f0, make_float2(pp.x, pp.y));
        f1 = cmul(f1, make_float2(pp.z, pp.w));
        a[i0] = cadd(f0, f1);
        a[i1] = csub(f0, f1);
    }
    __syncthreads();

    pass16_ip<2,  true>(a, tid); __syncthreads();
    pass16_ip<32, true>(a, tid); __syncthreads();

    // ---- DIT r16 @ S=512 fused with global store (keep j < 4096) ----
    {
        int j = tid;
        const float inv = 1.0f / (float)NFFT;
        float* o0 = out + b0 * OFEAT;
        float* o1 = o0 + OFEAT;
        float2 v[16];
        #pragma unroll
        for (int r = 0; r < 16; ++r) v[r] = a[PHYS(j + r * 512)];
        twmul16(v, j);
        dft16(v);
        #pragma unroll
        for (int r = 0; r < 8; ++r) {
            int jj = j + r * 512;                  // natural output index
            int o = OFEAT - 1 - jj;
            float bb = __ldg(bias + o);
            o0[o] = v[r].x * inv + bb;
            o1[o] = v[r].y * inv + bb;
        }
    }
}

// ------------------------- host launch -------------------------
extern "C" void kernel_launch(void* const* d_in, const int* in_sizes, int n_in,
                              void* d_out, int out_size) {
    const float* x    = (const float*)d_in[0];
    const float* p    = (const float*)d_in[1];
    const float* bias = (const float*)d_in[2];
    float* out        = (float*)d_out;
    (void)in_sizes; (void)n_in; (void)out_size;

    cudaFuncSetAttribute(prep_P_kernel,
                         cudaFuncAttributeMaxDynamicSharedMemorySize, SMEM_TOTAL);
    cudaFuncSetAttribute(fft_toeplitz_kernel,
                         cudaFuncAttributeMaxDynamicSharedMemorySize, SMEM_TOTAL);

    prep_P_kernel<<<1, NTHREADS, SMEM_TOTAL>>>(p);
    fft_toeplitz_kernel<<<BATCH_SZ / 2, NTHREADS, SMEM_TOTAL>>>(x, bias, out);
}

// round 14
// speedup vs baseline: 2.0277x; 1.0530x over previous
#include <cuda_runtime.h>
#include <cuda.h>
#include <cstdint>

// ===========================================================================
// LinearToeplitz via FFT correlation, in-place DIF->DIT, 2 CTAs/SM.
// out[b,o] = sum_i x[b,i] * p[i + (O-1-o)] + bias[o],  B=8192, I=O=4096.
// corr = (1/N) * FFT( FFT(z) .* conj(P) ),  z = x_a + i*x_b,  P = FFT(p_pad).
// R14: complex add/sub via packed f32x2 PTX (add.rn.f32x2 / fma.rn.f32x2)
//      -> ~27% fewer fp32 issues (issue pipe was the R13 wall at 66%).
//      Network unchanged: radix-16 [16,16,16,2], 7 phases, pad-16 layout.
// ===========================================================================

#define BATCH_SZ 8192
#define IFEAT    4096
#define OFEAT    4096
#define NFFT     8192
#define NTHREADS 512

__device__ __forceinline__ int PHYS(int i) { return i + (i >> 4); }
#define BUF_F2 8704
#define SMEM_TOTAL (BUF_F2 * 8)            // 69632 bytes -> 2 CTAs/SM

// ------------------------- global tables -------------------------
__device__ float2 g_tw[NFFT];   // e^{-2*pi*i*k/N}
__device__ float2 g_P[NFFT];    // conj(DIF(p_pad)) in DIF slot order

// ------------------------- complex helpers -------------------------
// packed f32x2: one instruction adds/fmas both components of a float2.
__device__ __forceinline__ float2 cadd(float2 a, float2 b) {
    unsigned long long au, bu, ru;
    au = *reinterpret_cast<unsigned long long*>(&a);
    bu = *reinterpret_cast<unsigned long long*>(&b);
    asm("add.rn.f32x2 %0, %1, %2;" : "=l"(ru) : "l"(au), "l"(bu));
    return *reinterpret_cast<float2*>(&ru);
}
__device__ __forceinline__ float2 csub(float2 a, float2 b) {
    // a - b = fma(b, (-1,-1), a)
    unsigned long long au, bu, ru;
    const unsigned long long m1 = 0xBF800000BF800000ull;   // (-1.f, -1.f)
    au = *reinterpret_cast<unsigned long long*>(&a);
    bu = *reinterpret_cast<unsigned long long*>(&b);
    asm("fma.rn.f32x2 %0, %1, %2, %3;" : "=l"(ru) : "l"(bu), "l"(m1), "l"(au));
    return *reinterpret_cast<float2*>(&ru);
}
__device__ __forceinline__ float2 cmul(float2 a, float2 b) {
    return make_float2(a.x * b.x - a.y * b.y, a.x * b.y + a.y * b.x);
}
__device__ __forceinline__ float2 cmni(float2 a) { return make_float2(a.y, -a.x); }

// forward DFT-8 (w8 = e^{-2pi i/8})
__device__ __forceinline__ void dft8(float2 v[8]) {
    const float S = 0.70710678118654752440f;
    float2 t0 = cadd(v[0], v[4]), t1 = csub(v[0], v[4]);
    float2 t2 = cadd(v[2], v[6]), t3 = cmni(csub(v[2], v[6]));
    float2 t4 = cadd(v[1], v[5]), t5 = csub(v[1], v[5]);
    float2 t6 = cadd(v[3], v[7]), t7 = cmni(csub(v[3], v[7]));
    float2 e0 = cadd(t0, t2), e1 = cadd(t1, t3), e2 = csub(t0, t2), e3 = csub(t1, t3);
    float2 o0 = cadd(t4, t6), o1 = cadd(t5, t7), o2 = csub(t4, t6), o3 = csub(t5, t7);
    o1 = cmul(o1, make_float2(S, -S));
    o2 = cmni(o2);
    o3 = cmul(o3, make_float2(-S, -S));
    v[0] = cadd(e0, o0); v[4] = csub(e0, o0);
    v[1] = cadd(e1, o1); v[5] = csub(e1, o1);
    v[2] = cadd(e2, o2); v[6] = csub(e2, o2);
    v[3] = cadd(e3, o3); v[7] = csub(e3, o3);
}

// forward DFT-16, natural in/out: split even/odd -> dft8 x2 -> combine.
__device__ __forceinline__ void dft16(float2 v[16]) {
    const float C1 = 0.92387953251128675613f;   // cos(pi/8)
    const float S1 = 0.38268343236508977173f;   // sin(pi/8)
    const float R  = 0.70710678118654752440f;
    float2 e[8], o[8];
    #pragma unroll
    for (int r = 0; r < 8; ++r) { e[r] = v[2 * r]; o[r] = v[2 * r + 1]; }
    dft8(e);
    dft8(o);
    o[1] = cmul(o[1], make_float2( C1, -S1));
    o[2] = cmul(o[2], make_float2(  R,  -R));
    o[3] = cmul(o[3], make_float2( S1, -C1));
    o[4] = cmni(o[4]);
    o[5] = cmul(o[5], make_float2(-S1, -C1));
    o[6] = cmul(o[6], make_float2( -R,  -R));
    o[7] = cmul(o[7], make_float2(-C1, -S1));
    #pragma unroll
    for (int k = 0; k < 8; ++k) {
        v[k]     = cadd(e[k], o[k]);
        v[k + 8] = csub(e[k], o[k]);
    }
}

// multiply v[1..15] by w^r from ONE table load (tree-built powers, depth 4).
__device__ __forceinline__ void twmul16(float2 v[16], int idx) {
    if (idx) {
        float2 w1 = g_tw[idx];
        float2 w2 = cmul(w1, w1);
        float2 w4 = cmul(w2, w2);
        float2 w8 = cmul(w4, w4);
        float2 w3 = cmul(w1, w2);
        float2 w5 = cmul(w1, w4);
        float2 w6 = cmul(w2, w4);
        float2 w7 = cmul(w3, w4);
        v[1]  = cmul(v[1],  w1);
        v[2]  = cmul(v[2],  w2);
        v[3]  = cmul(v[3],  w3);
        v[4]  = cmul(v[4],  w4);
        v[5]  = cmul(v[5],  w5);
        v[6]  = cmul(v[6],  w6);
        v[7]  = cmul(v[7],  w7);
        v[8]  = cmul(v[8],  w8);
        v[9]  = cmul(v[9],  cmul(w1, w8));
        v[10] = cmul(v[10], cmul(w2, w8));
        v[11] = cmul(v[11], cmul(w3, w8));
        v[12] = cmul(v[12], cmul(w4, w8));
        v[13] = cmul(v[13], cmul(w5, w8));
        v[14] = cmul(v[14], cmul(w6, w8));
        v[15] = cmul(v[15], cmul(w7, w8));
    }
}

// In-place radix-16 pass at span S. 512 butterflies == 512 threads (w = tid).
template <int S, bool PRE>
__device__ __forceinline__ void pass16_ip(float2* a, int w) {
    int q = w & (S - 1);
    int base = ((w & ~(S - 1)) << 4) + q;         // (w/S)*16S + q
    int idx = q * (NFFT / (16 * S));
    float2 v[16];
    #pragma unroll
    for (int r = 0; r < 16; ++r) v[r] = a[PHYS(base + r * S)];
    if (PRE) twmul16(v, idx);
    dft16(v);
    if (!PRE) twmul16(v, idx);
    #pragma unroll
    for (int r = 0; r < 16; ++r) a[PHYS(base + r * S)] = v[r];
}

// radix-2 at S=1 (no twiddle) — prep only
__device__ __forceinline__ void pass2_ip(float2* a, int tid) {
    #pragma unroll 1
    for (int s = 0; s < 8; ++s) {
        int m = tid + s * NTHREADS;
        int i0 = PHYS(2 * m), i1 = PHYS(2 * m + 1);
        float2 e0 = a[i0], e1 = a[i1];
        a[i0] = cadd(e0, e1);
        a[i1] = csub(e0, e1);
    }
}

// ------------------------- prep kernel -------------------------
__global__ void __launch_bounds__(NTHREADS, 2) prep_P_kernel(const float* __restrict__ p) {
    extern __shared__ __align__(16) float2 a[];
    const int tid = threadIdx.x;

    for (int k = tid; k < NFFT; k += NTHREADS) {
        float s, c;
        sincospif(-(float)k / 4096.0f, &s, &c);
        g_tw[k] = make_float2(c, s);
    }
    __threadfence();
    __syncthreads();

    for (int i = tid; i < NFFT; i += NTHREADS) {
        float v = (i < NFFT - 1) ? __ldg(p + i) : 0.f;
        a[PHYS(i)] = make_float2(v, 0.f);
    }
    __syncthreads();
    pass16_ip<512, false>(a, tid); __syncthreads();
    pass16_ip<32,  false>(a, tid); __syncthreads();
    pass16_ip<2,   false>(a, tid); __syncthreads();
    pass2_ip(a, tid);              __syncthreads();
    for (int i = tid; i < NFFT; i += NTHREADS) {
        float2 v = a[PHYS(i)];
        g_P[i] = make_float2(v.x, -v.y);
    }
}

// ------------------------- main kernel -------------------------
__global__ void __launch_bounds__(NTHREADS, 2) fft_toeplitz_kernel(
    const float* __restrict__ x,
    const float* __restrict__ bias,
    float* __restrict__ out)
{
    extern __shared__ __align__(16) float2 a[];
    const int tid = threadIdx.x;
    const size_t b0 = (size_t)blockIdx.x * 2;
    const float* xa = x + b0 * IFEAT;
    const float* xb = xa + IFEAT;

    // ---- DIF r16 @ S=512 fused with global load (r>=8 -> zero pad) ----
    {
        int j = tid;
        float2 v[16];
        #pragma unroll
        for (int r = 0; r < 8; ++r)
            v[r] = make_float2(__ldg(xa + j + r * 512), __ldg(xb + j + r * 512));
        #pragma unroll
        for (int r = 8; r < 16; ++r) v[r] = make_float2(0.f, 0.f);
        dft16(v);
        twmul16(v, j);
        #pragma unroll
        for (int r = 0; r < 16; ++r) a[PHYS(j + r * 512)] = v[r];
    }
    __syncthreads();

    pass16_ip<32, false>(a, tid); __syncthreads();
    pass16_ip<2,  false>(a, tid); __syncthreads();

    // ---- fused: DIF radix-2 + pointwise (.* g_P) + DIT radix-2 ----
    #pragma unroll 1
    for (int s = 0; s < 8; ++s) {
        int m = tid + s * NTHREADS;
        int i0 = PHYS(2 * m), i1 = PHYS(2 * m + 1);
        float2 e0 = a[i0], e1 = a[i1];
        float2 f0 = cadd(e0, e1), f1 = csub(e0, e1);
        float4 pp = *reinterpret_cast<const float4*>(g_P + 2 * m);
        f0 = cmul(f0, make_float2(pp.x, pp.y));
        f1 = cmul(f1, make_float2(pp.z, pp.w));
        a[i0] = cadd(f0, f1);
        a[i1] = csub(f0, f1);
    }
    __syncthreads();

    pass16_ip<2,  true>(a, tid); __syncthreads();
    pass16_ip<32, true>(a, tid); __syncthreads();

    // ---- DIT r16 @ S=512 fused with global store (keep j < 4096) ----
    {
        int j = tid;
        const float inv = 1.0f / (float)NFFT;
        float* o0 = out + b0 * OFEAT;
        float* o1 = o0 + OFEAT;
        float2 v[16];
        #pragma unroll
        for (int r = 0; r < 16; ++r) v[r] = a[PHYS(j + r * 512)];
        twmul16(v, j);
        dft16(v);
        #pragma unroll
        for (int r = 0; r < 8; ++r) {
            int jj = j + r * 512;
            int o = OFEAT - 1 - jj;
            float bb = __ldg(bias + o);
            o0[o] = v[r].x * inv + bb;
            o1[o] = v[r].y * inv + bb;
        }
    }
}

// ------------------------- host launch -------------------------
extern "C" void kernel_launch(void* const* d_in, const int* in_sizes, int n_in,
                              void* d_out, int out_size) {
    const float* x    = (const float*)d_in[0];
    const float* p    = (const float*)d_in[1];
    const float* bias = (const float*)d_in[2];
    float* out        = (float*)d_out;
    (void)in_sizes; (void)n_in; (void)out_size;

    cudaFuncSetAttribute(prep_P_kernel,
                         cudaFuncAttributeMaxDynamicSharedMemorySize, SMEM_TOTAL);
    cudaFuncSetAttribute(fft_toeplitz_kernel,
                         cudaFuncAttributeMaxDynamicSharedMemorySize, SMEM_TOTAL);

    prep_P_kernel<<<1, NTHREADS, SMEM_TOTAL>>>(p);
    fft_toeplitz_kernel<<<BATCH_SZ / 2, NTHREADS, SMEM_TOTAL>>>(x, bias, out);
}

// round 15
// speedup vs baseline: 2.2129x; 1.0913x over previous
#include <cuda_runtime.h>
#include <cuda.h>
#include <cstdint>

// ===========================================================================
// LinearToeplitz via FFT correlation, in-place DIF->DIT, 2 CTAs/SM.
// out[b,o] = sum_i x[b,i] * p[i + (O-1-o)] + bias[o],  B=8192, I=O=4096.
// corr = (1/N) * FFT( FFT(z) .* conj(P) ),  z = x_a + i*x_b,  P = FFT(p_pad).
// R15: after the S=512 pass the 5 middle phases are independent per
//      512-element block == per WARP. Replace 5 of 7 __syncthreads with
//      __syncwarp (no cross-warp lockstep). Addressing identical to R14.
// ===========================================================================

#define BATCH_SZ 8192
#define IFEAT    4096
#define OFEAT    4096
#define NFFT     8192
#define NTHREADS 512

__device__ __forceinline__ int PHYS(int i) { return i + (i >> 4); }
#define BUF_F2 8704
#define SMEM_TOTAL (BUF_F2 * 8)            // 69632 bytes -> 2 CTAs/SM

// ------------------------- global tables -------------------------
__device__ float2 g_tw[NFFT];   // e^{-2*pi*i*k/N}
__device__ float2 g_P[NFFT];    // conj(DIF(p_pad)) in DIF slot order

// ------------------------- complex helpers -------------------------
__device__ __forceinline__ float2 cadd(float2 a, float2 b) {
    unsigned long long au, bu, ru;
    au = *reinterpret_cast<unsigned long long*>(&a);
    bu = *reinterpret_cast<unsigned long long*>(&b);
    asm("add.rn.f32x2 %0, %1, %2;" : "=l"(ru) : "l"(au), "l"(bu));
    return *reinterpret_cast<float2*>(&ru);
}
__device__ __forceinline__ float2 csub(float2 a, float2 b) {
    unsigned long long au, bu, ru;
    const unsigned long long m1 = 0xBF800000BF800000ull;   // (-1.f, -1.f)
    au = *reinterpret_cast<unsigned long long*>(&a);
    bu = *reinterpret_cast<unsigned long long*>(&b);
    asm("fma.rn.f32x2 %0, %1, %2, %3;" : "=l"(ru) : "l"(bu), "l"(m1), "l"(au));
    return *reinterpret_cast<float2*>(&ru);
}
__device__ __forceinline__ float2 cmul(float2 a, float2 b) {
    return make_float2(a.x * b.x - a.y * b.y, a.x * b.y + a.y * b.x);
}
__device__ __forceinline__ float2 cmni(float2 a) { return make_float2(a.y, -a.x); }

// forward DFT-8 (w8 = e^{-2pi i/8})
__device__ __forceinline__ void dft8(float2 v[8]) {
    const float S = 0.70710678118654752440f;
    float2 t0 = cadd(v[0], v[4]), t1 = csub(v[0], v[4]);
    float2 t2 = cadd(v[2], v[6]), t3 = cmni(csub(v[2], v[6]));
    float2 t4 = cadd(v[1], v[5]), t5 = csub(v[1], v[5]);
    float2 t6 = cadd(v[3], v[7]), t7 = cmni(csub(v[3], v[7]));
    float2 e0 = cadd(t0, t2), e1 = cadd(t1, t3), e2 = csub(t0, t2), e3 = csub(t1, t3);
    float2 o0 = cadd(t4, t6), o1 = cadd(t5, t7), o2 = csub(t4, t6), o3 = csub(t5, t7);
    o1 = cmul(o1, make_float2(S, -S));
    o2 = cmni(o2);
    o3 = cmul(o3, make_float2(-S, -S));
    v[0] = cadd(e0, o0); v[4] = csub(e0, o0);
    v[1] = cadd(e1, o1); v[5] = csub(e1, o1);
    v[2] = cadd(e2, o2); v[6] = csub(e2, o2);
    v[3] = cadd(e3, o3); v[7] = csub(e3, o3);
}

// forward DFT-16, natural in/out: split even/odd -> dft8 x2 -> combine.
__device__ __forceinline__ void dft16(float2 v[16]) {
    const float C1 = 0.92387953251128675613f;   // cos(pi/8)
    const float S1 = 0.38268343236508977173f;   // sin(pi/8)
    const float R  = 0.70710678118654752440f;
    float2 e[8], o[8];
    #pragma unroll
    for (int r = 0; r < 8; ++r) { e[r] = v[2 * r]; o[r] = v[2 * r + 1]; }
    dft8(e);
    dft8(o);
    o[1] = cmul(o[1], make_float2( C1, -S1));
    o[2] = cmul(o[2], make_float2(  R,  -R));
    o[3] = cmul(o[3], make_float2( S1, -C1));
    o[4] = cmni(o[4]);
    o[5] = cmul(o[5], make_float2(-S1, -C1));
    o[6] = cmul(o[6], make_float2( -R,  -R));
    o[7] = cmul(o[7], make_float2(-C1, -S1));
    #pragma unroll
    for (int k = 0; k < 8; ++k) {
        v[k]     = cadd(e[k], o[k]);
        v[k + 8] = csub(e[k], o[k]);
    }
}

// multiply v[1..15] by w^r from ONE table load (tree-built powers, depth 4).
__device__ __forceinline__ void twmul16(float2 v[16], int idx) {
    if (idx) {
        float2 w1 = g_tw[idx];
        float2 w2 = cmul(w1, w1);
        float2 w4 = cmul(w2, w2);
        float2 w8 = cmul(w4, w4);
        float2 w3 = cmul(w1, w2);
        float2 w5 = cmul(w1, w4);
        float2 w6 = cmul(w2, w4);
        float2 w7 = cmul(w3, w4);
        v[1]  = cmul(v[1],  w1);
        v[2]  = cmul(v[2],  w2);
        v[3]  = cmul(v[3],  w3);
        v[4]  = cmul(v[4],  w4);
        v[5]  = cmul(v[5],  w5);
        v[6]  = cmul(v[6],  w6);
        v[7]  = cmul(v[7],  w7);
        v[8]  = cmul(v[8],  w8);
        v[9]  = cmul(v[9],  cmul(w1, w8));
        v[10] = cmul(v[10], cmul(w2, w8));
        v[11] = cmul(v[11], cmul(w3, w8));
        v[12] = cmul(v[12], cmul(w4, w8));
        v[13] = cmul(v[13], cmul(w5, w8));
        v[14] = cmul(v[14], cmul(w6, w8));
        v[15] = cmul(v[15], cmul(w7, w8));
    }
}

// In-place radix-16 pass at span S. 512 butterflies == 512 threads (w = tid).
template <int S, bool PRE>
__device__ __forceinline__ void pass16_ip(float2* a, int w) {
    int q = w & (S - 1);
    int base = ((w & ~(S - 1)) << 4) + q;         // (w/S)*16S + q
    int idx = q * (NFFT / (16 * S));
    float2 v[16];
    #pragma unroll
    for (int r = 0; r < 16; ++r) v[r] = a[PHYS(base + r * S)];
    if (PRE) twmul16(v, idx);
    dft16(v);
    if (!PRE) twmul16(v, idx);
    #pragma unroll
    for (int r = 0; r < 16; ++r) a[PHYS(base + r * S)] = v[r];
}

// radix-2 at S=1 (no twiddle) — prep only
__device__ __forceinline__ void pass2_ip(float2* a, int tid) {
    #pragma unroll 1
    for (int s = 0; s < 8; ++s) {
        int m = tid + s * NTHREADS;
        int i0 = PHYS(2 * m), i1 = PHYS(2 * m + 1);
        float2 e0 = a[i0], e1 = a[i1];
        a[i0] = cadd(e0, e1);
        a[i1] = csub(e0, e1);
    }
}

// ------------------------- prep kernel -------------------------
__global__ void __launch_bounds__(NTHREADS, 2) prep_P_kernel(const float* __restrict__ p) {
    extern __shared__ __align__(16) float2 a[];
    const int tid = threadIdx.x;

    for (int k = tid; k < NFFT; k += NTHREADS) {
        float s, c;
        sincospif(-(float)k / 4096.0f, &s, &c);
        g_tw[k] = make_float2(c, s);
    }
    __threadfence();
    __syncthreads();

    for (int i = tid; i < NFFT; i += NTHREADS) {
        float v = (i < NFFT - 1) ? __ldg(p + i) : 0.f;
        a[PHYS(i)] = make_float2(v, 0.f);
    }
    __syncthreads();
    pass16_ip<512, false>(a, tid); __syncthreads();
    pass16_ip<32,  false>(a, tid); __syncthreads();
    pass16_ip<2,   false>(a, tid); __syncthreads();
    pass2_ip(a, tid);              __syncthreads();
    for (int i = tid; i < NFFT; i += NTHREADS) {
        float2 v = a[PHYS(i)];
        g_P[i] = make_float2(v.x, -v.y);
    }
}

// ------------------------- main kernel -------------------------
__global__ void __launch_bounds__(NTHREADS, 2) fft_toeplitz_kernel(
    const float* __restrict__ x,
    const float* __restrict__ bias,
    float* __restrict__ out)
{
    extern __shared__ __align__(16) float2 a[];
    const int tid  = threadIdx.x;
    const int wid  = tid >> 5;
    const int lane = tid & 31;
    const size_t b0 = (size_t)blockIdx.x * 2;
    const float* xa = x + b0 * IFEAT;
    const float* xb = xa + IFEAT;

    // ---- DIF r16 @ S=512 fused with global load (r>=8 -> zero pad) ----
    {
        int j = tid;
        float2 v[16];
        #pragma unroll
        for (int r = 0; r < 8; ++r)
            v[r] = make_float2(__ldg(xa + j + r * 512), __ldg(xb + j + r * 512));
        #pragma unroll
        for (int r = 8; r < 16; ++r) v[r] = make_float2(0.f, 0.f);
        dft16(v);
        twmul16(v, j);
        #pragma unroll
        for (int r = 0; r < 16; ++r) a[PHYS(j + r * 512)] = v[r];
    }
    __syncthreads();

    // ---- middle phases: independent per 512-block == per warp ----
    pass16_ip<32, false>(a, tid); __syncwarp();
    pass16_ip<2,  false>(a, tid); __syncwarp();

    // fused: DIF radix-2 + pointwise (.* g_P) + DIT radix-2
    // warp wid owns pairs m in [256*wid, 256*wid+256)
    {
        int mbase = (wid << 8) + lane;
        #pragma unroll 1
        for (int s = 0; s < 8; ++s) {
            int m = mbase + (s << 5);
            int i0 = PHYS(2 * m), i1 = PHYS(2 * m + 1);
            float2 e0 = a[i0], e1 = a[i1];
            float2 f0 = cadd(e0, e1), f1 = csub(e0, e1);
            float4 pp = *reinterpret_cast<const float4*>(g_P + 2 * m);
            f0 = cmul(f0, make_float2(pp.x, pp.y));
            f1 = cmul(f1, make_float2(pp.z, pp.w));
            a[i0] = cadd(f0, f1);
            a[i1] = csub(f0, f1);
        }
    }
    __syncwarp();

    pass16_ip<2,  true>(a, tid); __syncwarp();
    pass16_ip<32, true>(a, tid);
    __syncthreads();

    // ---- DIT r16 @ S=512 fused with global store (keep j < 4096) ----
    {
        int j = tid;
        const float inv = 1.0f / (float)NFFT;
        float* o0 = out + b0 * OFEAT;
        float* o1 = o0 + OFEAT;
        float2 v[16];
        #pragma unroll
        for (int r = 0; r < 16; ++r) v[r] = a[PHYS(j + r * 512)];
        twmul16(v, j);
        dft16(v);
        #pragma unroll
        for (int r = 0; r < 8; ++r) {
            int jj = j + r * 512;
            int o = OFEAT - 1 - jj;
            float bb = __ldg(bias + o);
            o0[o] = v[r].x * inv + bb;
            o1[o] = v[r].y * inv + bb;
        }
    }
}

// ------------------------- host launch -------------------------
extern "C" void kernel_launch(void* const* d_in, const int* in_sizes, int n_in,
                              void* d_out, int out_size) {
    const float* x    = (const float*)d_in[0];
    const float* p    = (const float*)d_in[1];
    const float* bias = (const float*)d_in[2];
    float* out        = (float*)d_out;
    (void)in_sizes; (void)n_in; (void)out_size;

    cudaFuncSetAttribute(prep_P_kernel,
                         cudaFuncAttributeMaxDynamicSharedMemorySize, SMEM_TOTAL);
    cudaFuncSetAttribute(fft_toeplitz_kernel,
                         cudaFuncAttributeMaxDynamicSharedMemorySize, SMEM_TOTAL);

    prep_P_kernel<<<1, NTHREADS, SMEM_TOTAL>>>(p);
    fft_toeplitz_kernel<<<BATCH_SZ / 2, NTHREADS, SMEM_TOTAL>>>(x, bias, out);
}

// round 16
// speedup vs baseline: 2.2692x; 1.0254x over previous
#include <cuda_runtime.h>
#include <cuda.h>
#include <cstdint>

// ===========================================================================
// LinearToeplitz via FFT correlation, in-place DIF->DIT, 2 CTAs/SM.
// out[b,o] = sum_i x[b,i] * p[i + (O-1-o)] + bias[o],  B=8192, I=O=4096.
// corr = (1/N) * FFT( FFT(z) .* conj(P) ),  z = x_a + i*x_b.
// R16: 5 smem phases (was 7). The inner [r16@S2 DIF, r2, pointwise, r2,
//      r16@S2 DIT] collapses into ONE register phase: the r2+pw+r2 core is a
//      precomputed 2x2 symmetric matrix  y_q = A*u_q + B*u_partner
//      (A = Pc0+Pc1, B = Pc0-Pc1, table g_AB), partner value via shfl.xor(1).
// ===========================================================================

#define BATCH_SZ 8192
#define IFEAT    4096
#define OFEAT    4096
#define NFFT     8192
#define NTHREADS 512

__device__ __forceinline__ int PHYS(int i) { return i + (i >> 4); }
#define BUF_F2 8704
#define SMEM_TOTAL (BUF_F2 * 8)            // 69632 bytes -> 2 CTAs/SM

// ------------------------- global tables -------------------------
__device__ float2 g_tw[NFFT];    // e^{-2*pi*i*k/N}
__device__ float4 g_AB[NFFT/2];  // composite 2x2 per pair, layout [r*256+blk]

// ------------------------- complex helpers -------------------------
__device__ __forceinline__ float2 cadd(float2 a, float2 b) {
    unsigned long long au, bu, ru;
    au = *reinterpret_cast<unsigned long long*>(&a);
    bu = *reinterpret_cast<unsigned long long*>(&b);
    asm("add.rn.f32x2 %0, %1, %2;" : "=l"(ru) : "l"(au), "l"(bu));
    return *reinterpret_cast<float2*>(&ru);
}
__device__ __forceinline__ float2 csub(float2 a, float2 b) {
    unsigned long long au, bu, ru;
    const unsigned long long m1 = 0xBF800000BF800000ull;   // (-1.f, -1.f)
    au = *reinterpret_cast<unsigned long long*>(&a);
    bu = *reinterpret_cast<unsigned long long*>(&b);
    asm("fma.rn.f32x2 %0, %1, %2, %3;" : "=l"(ru) : "l"(bu), "l"(m1), "l"(au));
    return *reinterpret_cast<float2*>(&ru);
}
__device__ __forceinline__ float2 cmul(float2 a, float2 b) {
    return make_float2(a.x * b.x - a.y * b.y, a.x * b.y + a.y * b.x);
}
__device__ __forceinline__ float2 cmni(float2 a) { return make_float2(a.y, -a.x); }

// forward DFT-8 (w8 = e^{-2pi i/8})
__device__ __forceinline__ void dft8(float2 v[8]) {
    const float S = 0.70710678118654752440f;
    float2 t0 = cadd(v[0], v[4]), t1 = csub(v[0], v[4]);
    float2 t2 = cadd(v[2], v[6]), t3 = cmni(csub(v[2], v[6]));
    float2 t4 = cadd(v[1], v[5]), t5 = csub(v[1], v[5]);
    float2 t6 = cadd(v[3], v[7]), t7 = cmni(csub(v[3], v[7]));
    float2 e0 = cadd(t0, t2), e1 = cadd(t1, t3), e2 = csub(t0, t2), e3 = csub(t1, t3);
    float2 o0 = cadd(t4, t6), o1 = cadd(t5, t7), o2 = csub(t4, t6), o3 = csub(t5, t7);
    o1 = cmul(o1, make_float2(S, -S));
    o2 = cmni(o2);
    o3 = cmul(o3, make_float2(-S, -S));
    v[0] = cadd(e0, o0); v[4] = csub(e0, o0);
    v[1] = cadd(e1, o1); v[5] = csub(e1, o1);
    v[2] = cadd(e2, o2); v[6] = csub(e2, o2);
    v[3] = cadd(e3, o3); v[7] = csub(e3, o3);
}

// forward DFT-16, natural in/out
__device__ __forceinline__ void dft16(float2 v[16]) {
    const float C1 = 0.92387953251128675613f;
    const float S1 = 0.38268343236508977173f;
    const float R  = 0.70710678118654752440f;
    float2 e[8], o[8];
    #pragma unroll
    for (int r = 0; r < 8; ++r) { e[r] = v[2 * r]; o[r] = v[2 * r + 1]; }
    dft8(e);
    dft8(o);
    o[1] = cmul(o[1], make_float2( C1, -S1));
    o[2] = cmul(o[2], make_float2(  R,  -R));
    o[3] = cmul(o[3], make_float2( S1, -C1));
    o[4] = cmni(o[4]);
    o[5] = cmul(o[5], make_float2(-S1, -C1));
    o[6] = cmul(o[6], make_float2( -R,  -R));
    o[7] = cmul(o[7], make_float2(-C1, -S1));
    #pragma unroll
    for (int k = 0; k < 8; ++k) {
        v[k]     = cadd(e[k], o[k]);
        v[k + 8] = csub(e[k], o[k]);
    }
}

// multiply v[1..15] by w^r from ONE table load (tree-built powers)
__device__ __forceinline__ void twmul16(float2 v[16], int idx) {
    if (idx) {
        float2 w1 = g_tw[idx];
        float2 w2 = cmul(w1, w1);
        float2 w4 = cmul(w2, w2);
        float2 w8 = cmul(w4, w4);
        float2 w3 = cmul(w1, w2);
        float2 w5 = cmul(w1, w4);
        float2 w6 = cmul(w2, w4);
        float2 w7 = cmul(w3, w4);
        v[1]  = cmul(v[1],  w1);
        v[2]  = cmul(v[2],  w2);
        v[3]  = cmul(v[3],  w3);
        v[4]  = cmul(v[4],  w4);
        v[5]  = cmul(v[5],  w5);
        v[6]  = cmul(v[6],  w6);
        v[7]  = cmul(v[7],  w7);
        v[8]  = cmul(v[8],  w8);
        v[9]  = cmul(v[9],  cmul(w1, w8));
        v[10] = cmul(v[10], cmul(w2, w8));
        v[11] = cmul(v[11], cmul(w3, w8));
        v[12] = cmul(v[12], cmul(w4, w8));
        v[13] = cmul(v[13], cmul(w5, w8));
        v[14] = cmul(v[14], cmul(w6, w8));
        v[15] = cmul(v[15], cmul(w7, w8));
    }
}

// In-place radix-16 pass at span S. 512 butterflies == 512 threads (w = tid).
template <int S, bool PRE>
__device__ __forceinline__ void pass16_ip(float2* a, int w) {
    int q = w & (S - 1);
    int base = ((w & ~(S - 1)) << 4) + q;
    int idx = q * (NFFT / (16 * S));
    float2 v[16];
    #pragma unroll
    for (int r = 0; r < 16; ++r) v[r] = a[PHYS(base + r * S)];
    if (PRE) twmul16(v, idx);
    dft16(v);
    if (!PRE) twmul16(v, idx);
    #pragma unroll
    for (int r = 0; r < 16; ++r) a[PHYS(base + r * S)] = v[r];
}

// radix-2 at S=1 (no twiddle) — prep only
__device__ __forceinline__ void pass2_ip(float2* a, int tid) {
    #pragma unroll 1
    for (int s = 0; s < 8; ++s) {
        int m = tid + s * NTHREADS;
        int i0 = PHYS(2 * m), i1 = PHYS(2 * m + 1);
        float2 e0 = a[i0], e1 = a[i1];
        a[i0] = cadd(e0, e1);
        a[i1] = csub(e0, e1);
    }
}

// ------------------------- prep kernel -------------------------
// Fills g_tw, runs the full DIF on p_pad, then stores the pair-composite
// A = conj(P0)+conj(P1), B = conj(P0)-conj(P1) in [r*256+blk] layout.
__global__ void __launch_bounds__(NTHREADS, 2) prep_P_kernel(const float* __restrict__ p) {
    extern __shared__ __align__(16) float2 a[];
    const int tid = threadIdx.x;

    for (int k = tid; k < NFFT; k += NTHREADS) {
        float s, c;
        sincospif(-(float)k / 4096.0f, &s, &c);
        g_tw[k] = make_float2(c, s);
    }
    __threadfence();
    __syncthreads();

    for (int i = tid; i < NFFT; i += NTHREADS) {
        float v = (i < NFFT - 1) ? __ldg(p + i) : 0.f;
        a[PHYS(i)] = make_float2(v, 0.f);
    }
    __syncthreads();
    pass16_ip<512, false>(a, tid); __syncthreads();
    pass16_ip<32,  false>(a, tid); __syncthreads();
    pass16_ip<2,   false>(a, tid); __syncthreads();
    pass2_ip(a, tid);              __syncthreads();

    for (int m = tid; m < NFFT / 2; m += NTHREADS) {
        float2 p0 = a[PHYS(2 * m)];
        float2 p1 = a[PHYS(2 * m + 1)];
        p0.y = -p0.y;                       // conj
        p1.y = -p1.y;
        float2 A = cadd(p0, p1);
        float2 B = csub(p0, p1);
        g_AB[((m & 15) << 8) + (m >> 4)] = make_float4(A.x, A.y, B.x, B.y);
    }
}

// ------------------------- main kernel -------------------------
__global__ void __launch_bounds__(NTHREADS, 2) fft_toeplitz_kernel(
    const float* __restrict__ x,
    const float* __restrict__ bias,
    float* __restrict__ out)
{
    extern __shared__ __align__(16) float2 a[];
    const int tid  = threadIdx.x;
    const size_t b0 = (size_t)blockIdx.x * 2;
    const float* xa = x + b0 * IFEAT;
    const float* xb = xa + IFEAT;

    // ---- P1: DIF r16 @ S=512 fused with global load (r>=8 -> zero pad) ----
    {
        int j = tid;
        float2 v[16];
        #pragma unroll
        for (int r = 0; r < 8; ++r)
            v[r] = make_float2(__ldg(xa + j + r * 512), __ldg(xb + j + r * 512));
        #pragma unroll
        for (int r = 8; r < 16; ++r) v[r] = make_float2(0.f, 0.f);
        dft16(v);
        twmul16(v, j);
        #pragma unroll
        for (int r = 0; r < 16; ++r) a[PHYS(j + r * 512)] = v[r];
    }
    __syncthreads();

    // ---- P2: DIF r16 @ S=32 (warp-local) ----
    pass16_ip<32, false>(a, tid); __syncwarp();

    // ---- P3: FUSED  r16@S2(DIF) + [r2+pw+r2 == 2x2 composite] + r16@S2(DIT)
    // Thread pair (q = w&1) exchanges partner values once via shfl.xor(1).
    {
        int w = tid;
        int q   = w & 1;
        int blk = w >> 1;                     // [0, 256)
        int base = (blk << 5) + q;
        int idx  = q << 8;                    // q * 256
        float2 v[16];
        #pragma unroll
        for (int r = 0; r < 16; ++r) v[r] = a[PHYS(base + 2 * r)];
        dft16(v);
        twmul16(v, idx);                      // DIF twiddle (after)
        #pragma unroll
        for (int r = 0; r < 16; ++r) {
            float2 u = v[r];
            float2 uo;
            uo.x = __shfl_xor_sync(0xffffffffu, u.x, 1);
            uo.y = __shfl_xor_sync(0xffffffffu, u.y, 1);
            float4 ab = __ldg(&g_AB[(r << 8) + blk]);
            v[r] = cadd(cmul(make_float2(ab.x, ab.y), u),
                        cmul(make_float2(ab.z, ab.w), uo));
        }
        twmul16(v, idx);                      // DIT twiddle (before)
        dft16(v);
        #pragma unroll
        for (int r = 0; r < 16; ++r) a[PHYS(base + 2 * r)] = v[r];
    }
    __syncwarp();

    // ---- P4: DIT r16 @ S=32 (warp-local) ----
    pass16_ip<32, true>(a, tid);
    __syncthreads();

    // ---- P5: DIT r16 @ S=512 fused with global store (keep j < 4096) ----
    {
        int j = tid;
        const float inv = 1.0f / (float)NFFT;
        float* o0 = out + b0 * OFEAT;
        float* o1 = o0 + OFEAT;
        float2 v[16];
        #pragma unroll
        for (int r = 0; r < 16; ++r) v[r] = a[PHYS(j + r * 512)];
        twmul16(v, j);
        dft16(v);
        #pragma unroll
        for (int r = 0; r < 8; ++r) {
            int jj = j + r * 512;
            int o = OFEAT - 1 - jj;
            float bb = __ldg(bias + o);
            o0[o] = v[r].x * inv + bb;
            o1[o] = v[r].y * inv + bb;
        }
    }
}

// ------------------------- host launch -------------------------
extern "C" void kernel_launch(void* const* d_in, const int* in_sizes, int n_in,
                              void* d_out, int out_size) {
    const float* x    = (const float*)d_in[0];
    const float* p    = (const float*)d_in[1];
    const float* bias = (const float*)d_in[2];
    float* out        = (float*)d_out;
    (void)in_sizes; (void)n_in; (void)out_size;

    cudaFuncSetAttribute(prep_P_kernel,
                         cudaFuncAttributeMaxDynamicSharedMemorySize, SMEM_TOTAL);
    cudaFuncSetAttribute(fft_toeplitz_kernel,
                         cudaFuncAttributeMaxDynamicSharedMemorySize, SMEM_TOTAL);

    prep_P_kernel<<<1, NTHREADS, SMEM_TOTAL>>>(p);
    fft_toeplitz_kernel<<<BATCH_SZ / 2, NTHREADS, SMEM_TOTAL>>>(x, bias, out);
}

// round 17
// speedup vs baseline: 2.4311x; 1.0714x over previous
#include <cuda_runtime.h>
#include <cuda.h>
#include <cstdint>

// ===========================================================================
// LinearToeplitz via FFT correlation, in-place DIF->DIT, 2 CTAs/SM.
// out[b,o] = sum_i x[b,i] * p[i + (O-1-o)] + bias[o],  B=8192, I=O=4096.
// corr = (1/N) * FFT( FFT(z) .* conj(P) ),  z = x_a + i*x_b.
// R17: twiddle powers from precomputed tables (coalesced LDG) instead of
//      register product chains; P3 twiddles are compile-time constants.
//      ~29 cmuls/call -> 15 cmuls + 15 coalesced loads. fma pipe was 57%.
// Phases: P1 load+r16@512 | P2 r16@32 | P3 fused(r16@2+2x2+r16@2) |
//         P4 r16@32 | P5 r16@512+store.  Pad-16 smem, 2 CTAs/SM.
// ===========================================================================

#define BATCH_SZ 8192
#define IFEAT    4096
#define OFEAT    4096
#define NFFT     8192
#define NTHREADS 512

__device__ __forceinline__ int PHYS(int i) { return i + (i >> 4); }
#define BUF_F2 8704
#define SMEM_TOTAL (BUF_F2 * 8)            // 69632 bytes -> 2 CTAs/SM

// ------------------------- global tables -------------------------
__device__ float2 g_tw[NFFT];        // e^{-2*pi*i*k/N} (prep + table build)
__device__ float4 g_AB[NFFT / 2];    // composite 2x2 per pair [r*256+blk]
__device__ float2 g_tw15[15 * 512];  // P1/P5: [k-1][j]   = e^{-2pi i jk/8192}
__device__ float2 g_tw24[15 * 32];   // P2/P4: [k-1][lane]= e^{-2pi i 16*lane*k/8192}

// ------------------------- complex helpers -------------------------
__device__ __forceinline__ float2 cadd(float2 a, float2 b) {
    unsigned long long au, bu, ru;
    au = *reinterpret_cast<unsigned long long*>(&a);
    bu = *reinterpret_cast<unsigned long long*>(&b);
    asm("add.rn.f32x2 %0, %1, %2;" : "=l"(ru) : "l"(au), "l"(bu));
    return *reinterpret_cast<float2*>(&ru);
}
__device__ __forceinline__ float2 csub(float2 a, float2 b) {
    unsigned long long au, bu, ru;
    const unsigned long long m1 = 0xBF800000BF800000ull;
    au = *reinterpret_cast<unsigned long long*>(&a);
    bu = *reinterpret_cast<unsigned long long*>(&b);
    asm("fma.rn.f32x2 %0, %1, %2, %3;" : "=l"(ru) : "l"(bu), "l"(m1), "l"(au));
    return *reinterpret_cast<float2*>(&ru);
}
__device__ __forceinline__ float2 cmul(float2 a, float2 b) {
    return make_float2(a.x * b.x - a.y * b.y, a.x * b.y + a.y * b.x);
}
__device__ __forceinline__ float2 cmni(float2 a) { return make_float2(a.y, -a.x); }

// forward DFT-8
__device__ __forceinline__ void dft8(float2 v[8]) {
    const float S = 0.70710678118654752440f;
    float2 t0 = cadd(v[0], v[4]), t1 = csub(v[0], v[4]);
    float2 t2 = cadd(v[2], v[6]), t3 = cmni(csub(v[2], v[6]));
    float2 t4 = cadd(v[1], v[5]), t5 = csub(v[1], v[5]);
    float2 t6 = cadd(v[3], v[7]), t7 = cmni(csub(v[3], v[7]));
    float2 e0 = cadd(t0, t2), e1 = cadd(t1, t3), e2 = csub(t0, t2), e3 = csub(t1, t3);
    float2 o0 = cadd(t4, t6), o1 = cadd(t5, t7), o2 = csub(t4, t6), o3 = csub(t5, t7);
    o1 = cmul(o1, make_float2(S, -S));
    o2 = cmni(o2);
    o3 = cmul(o3, make_float2(-S, -S));
    v[0] = cadd(e0, o0); v[4] = csub(e0, o0);
    v[1] = cadd(e1, o1); v[5] = csub(e1, o1);
    v[2] = cadd(e2, o2); v[6] = csub(e2, o2);
    v[3] = cadd(e3, o3); v[7] = csub(e3, o3);
}

// forward DFT-16, natural in/out
__device__ __forceinline__ void dft16(float2 v[16]) {
    const float C1 = 0.92387953251128675613f;
    const float S1 = 0.38268343236508977173f;
    const float R  = 0.70710678118654752440f;
    float2 e[8], o[8];
    #pragma unroll
    for (int r = 0; r < 8; ++r) { e[r] = v[2 * r]; o[r] = v[2 * r + 1]; }
    dft8(e);
    dft8(o);
    o[1] = cmul(o[1], make_float2( C1, -S1));
    o[2] = cmul(o[2], make_float2(  R,  -R));
    o[3] = cmul(o[3], make_float2( S1, -C1));
    o[4] = cmni(o[4]);
    o[5] = cmul(o[5], make_float2(-S1, -C1));
    o[6] = cmul(o[6], make_float2( -R,  -R));
    o[7] = cmul(o[7], make_float2(-C1, -S1));
    #pragma unroll
    for (int k = 0; k < 8; ++k) {
        v[k]     = cadd(e[k], o[k]);
        v[k + 8] = csub(e[k], o[k]);
    }
}

// table-based twiddle: 15 coalesced loads, 15 cmuls (row k-1, column j)
template <int DIM>
__device__ __forceinline__ void twmul16_tbl(float2 v[16], const float2* t, int j) {
    float2 w[15];
    #pragma unroll
    for (int k = 0; k < 15; ++k) w[k] = __ldg(&t[k * DIM + j]);
    #pragma unroll
    for (int k = 0; k < 15; ++k) v[k + 1] = cmul(v[k + 1], w[k]);
}

// P3 twiddles are compile-time constants: w^k = e^{-i pi k/16}
__device__ __forceinline__ void twmul16_c(float2 v[16]) {
    const float c[15] = { 0.980785280403230449f,  0.923879532511286756f,
                          0.831469612302545237f,  0.707106781186547524f,
                          0.555570233019602225f,  0.382683432365089772f,
                          0.195090322016128268f,  0.f,
                         -0.195090322016128268f, -0.382683432365089772f,
                         -0.555570233019602225f, -0.707106781186547524f,
                         -0.831469612302545237f, -0.923879532511286756f,
                         -0.980785280403230449f };
    const float s[15] = { 0.195090322016128268f,  0.382683432365089772f,
                          0.555570233019602225f,  0.707106781186547524f,
                          0.831469612302545237f,  0.923879532511286756f,
                          0.980785280403230449f,  1.f,
                          0.980785280403230449f,  0.923879532511286756f,
                          0.831469612302545237f,  0.707106781186547524f,
                          0.555570233019602225f,  0.382683432365089772f,
                          0.195090322016128268f };
    #pragma unroll
    for (int k = 0; k < 15; ++k)
        v[k + 1] = cmul(v[k + 1], make_float2(c[k], -s[k]));
}

// register-built twiddle (prep only; runs once)
__device__ __forceinline__ void twmul16(float2 v[16], int idx) {
    if (idx) {
        float2 w1 = g_tw[idx];
        float2 w2 = cmul(w1, w1);
        float2 w4 = cmul(w2, w2);
        float2 w8 = cmul(w4, w4);
        float2 w3 = cmul(w1, w2);
        float2 w5 = cmul(w1, w4);
        float2 w6 = cmul(w2, w4);
        float2 w7 = cmul(w3, w4);
        v[1]  = cmul(v[1],  w1);  v[2]  = cmul(v[2],  w2);
        v[3]  = cmul(v[3],  w3);  v[4]  = cmul(v[4],  w4);
        v[5]  = cmul(v[5],  w5);  v[6]  = cmul(v[6],  w6);
        v[7]  = cmul(v[7],  w7);  v[8]  = cmul(v[8],  w8);
        v[9]  = cmul(v[9],  cmul(w1, w8));
        v[10] = cmul(v[10], cmul(w2, w8));
        v[11] = cmul(v[11], cmul(w3, w8));
        v[12] = cmul(v[12], cmul(w4, w8));
        v[13] = cmul(v[13], cmul(w5, w8));
        v[14] = cmul(v[14], cmul(w6, w8));
        v[15] = cmul(v[15], cmul(w7, w8));
    }
}

// In-place radix-16 pass at span S (prep; register-built twiddles)
template <int S, bool PRE>
__device__ __forceinline__ void pass16_ip(float2* a, int w) {
    int q = w & (S - 1);
    int base = ((w & ~(S - 1)) << 4) + q;
    int idx = q * (NFFT / (16 * S));
    float2 v[16];
    #pragma unroll
    for (int r = 0; r < 16; ++r) v[r] = a[PHYS(base + r * S)];
    if (PRE) twmul16(v, idx);
    dft16(v);
    if (!PRE) twmul16(v, idx);
    #pragma unroll
    for (int r = 0; r < 16; ++r) a[PHYS(base + r * S)] = v[r];
}

// In-place radix-16 pass @S=32, table twiddles (main kernel P2/P4)
template <bool PRE>
__device__ __forceinline__ void pass16_32t(float2* a, int w) {
    int q = w & 31;
    int base = ((w & ~31) << 4) + q;
    float2 v[16];
    #pragma unroll
    for (int r = 0; r < 16; ++r) v[r] = a[PHYS(base + r * 32)];
    if (PRE) twmul16_tbl<32>(v, g_tw24, q);
    dft16(v);
    if (!PRE) twmul16_tbl<32>(v, g_tw24, q);
    #pragma unroll
    for (int r = 0; r < 16; ++r) a[PHYS(base + r * 32)] = v[r];
}

// radix-2 at S=1 (no twiddle) — prep only
__device__ __forceinline__ void pass2_ip(float2* a, int tid) {
    #pragma unroll 1
    for (int s = 0; s < 8; ++s) {
        int m = tid + s * NTHREADS;
        int i0 = PHYS(2 * m), i1 = PHYS(2 * m + 1);
        float2 e0 = a[i0], e1 = a[i1];
        a[i0] = cadd(e0, e1);
        a[i1] = csub(e0, e1);
    }
}

// ------------------------- prep kernel -------------------------
__global__ void __launch_bounds__(NTHREADS, 2) prep_P_kernel(const float* __restrict__ p) {
    extern __shared__ __align__(16) float2 a[];
    const int tid = threadIdx.x;

    for (int k = tid; k < NFFT; k += NTHREADS) {
        float s, c;
        sincospif(-(float)k / 4096.0f, &s, &c);
        g_tw[k] = make_float2(c, s);
    }
    __threadfence();
    __syncthreads();

    // twiddle tables
    for (int i = tid; i < 15 * 512; i += NTHREADS) {
        int k = i / 512 + 1, j = i % 512;
        g_tw15[i] = g_tw[(j * k) & (NFFT - 1)];
    }
    for (int i = tid; i < 15 * 32; i += NTHREADS) {
        int k = i / 32 + 1, q = i % 32;
        g_tw24[i] = g_tw[(16 * q * k) & (NFFT - 1)];
    }

    // DIF of p_pad (slot order), then pair-composite A/B
    for (int i = tid; i < NFFT; i += NTHREADS) {
        float v = (i < NFFT - 1) ? __ldg(p + i) : 0.f;
        a[PHYS(i)] = make_float2(v, 0.f);
    }
    __syncthreads();
    pass16_ip<512, false>(a, tid); __syncthreads();
    pass16_ip<32,  false>(a, tid); __syncthreads();
    pass16_ip<2,   false>(a, tid); __syncthreads();
    pass2_ip(a, tid);              __syncthreads();

    for (int m = tid; m < NFFT / 2; m += NTHREADS) {
        float2 p0 = a[PHYS(2 * m)];
        float2 p1 = a[PHYS(2 * m + 1)];
        p0.y = -p0.y;
        p1.y = -p1.y;
        float2 A = cadd(p0, p1);
        float2 B = csub(p0, p1);
        g_AB[((m & 15) << 8) + (m >> 4)] = make_float4(A.x, A.y, B.x, B.y);
    }
}

// ------------------------- main kernel -------------------------
__global__ void __launch_bounds__(NTHREADS, 2) fft_toeplitz_kernel(
    const float* __restrict__ x,
    const float* __restrict__ bias,
    float* __restrict__ out)
{
    extern __shared__ __align__(16) float2 a[];
    const int tid  = threadIdx.x;
    const size_t b0 = (size_t)blockIdx.x * 2;
    const float* xa = x + b0 * IFEAT;
    const float* xb = xa + IFEAT;

    // ---- P1: DIF r16 @ S=512 fused with global load (r>=8 -> zero pad) ----
    {
        int j = tid;
        float2 v[16];
        #pragma unroll
        for (int r = 0; r < 8; ++r)
            v[r] = make_float2(__ldg(xa + j + r * 512), __ldg(xb + j + r * 512));
        #pragma unroll
        for (int r = 8; r < 16; ++r) v[r] = make_float2(0.f, 0.f);
        dft16(v);
        twmul16_tbl<512>(v, g_tw15, j);
        #pragma unroll
        for (int r = 0; r < 16; ++r) a[PHYS(j + r * 512)] = v[r];
    }
    __syncthreads();

    // ---- P2: DIF r16 @ S=32 (warp-local, table twiddles) ----
    pass16_32t<false>(a, tid); __syncwarp();

    // ---- P3: FUSED r16@S2(DIF) + 2x2 composite + r16@S2(DIT), const tw ----
    {
        int w = tid;
        int q   = w & 1;
        int blk = w >> 1;
        int base = (blk << 5) + q;
        float2 v[16];
        #pragma unroll
        for (int r = 0; r < 16; ++r) v[r] = a[PHYS(base + 2 * r)];
        dft16(v);
        if (q) twmul16_c(v);                  // DIF twiddle (after)
        #pragma unroll
        for (int r = 0; r < 16; ++r) {
            float2 u = v[r];
            float2 uo;
            uo.x = __shfl_xor_sync(0xffffffffu, u.x, 1);
            uo.y = __shfl_xor_sync(0xffffffffu, u.y, 1);
            float4 ab = __ldg(&g_AB[(r << 8) + blk]);
            v[r] = cadd(cmul(make_float2(ab.x, ab.y), u),
                        cmul(make_float2(ab.z, ab.w), uo));
        }
        if (q) twmul16_c(v);                  // DIT twiddle (before)
        dft16(v);
        #pragma unroll
        for (int r = 0; r < 16; ++r) a[PHYS(base + 2 * r)] = v[r];
    }
    __syncwarp();

    // ---- P4: DIT r16 @ S=32 (warp-local, table twiddles) ----
    pass16_32t<true>(a, tid);
    __syncthreads();

    // ---- P5: DIT r16 @ S=512 fused with global store (keep j < 4096) ----
    {
        int j = tid;
        const float inv = 1.0f / (float)NFFT;
        float* o0 = out + b0 * OFEAT;
        float* o1 = o0 + OFEAT;
        float2 v[16];
        #pragma unroll
        for (int r = 0; r < 16; ++r) v[r] = a[PHYS(j + r * 512)];
        twmul16_tbl<512>(v, g_tw15, j);
        dft16(v);
        #pragma unroll
        for (int r = 0; r < 8; ++r) {
            int jj = j + r * 512;
            int o = OFEAT - 1 - jj;
            float bb = __ldg(bias + o);
            o0[o] = v[r].x * inv + bb;
            o1[o] = v[r].y * inv + bb;
        }
    }
}

// ------------------------- host launch -------------------------
extern "C" void kernel_launch(void* const* d_in, const int* in_sizes, int n_in,
                              void* d_out, int out_size) {
    const float* x    = (const float*)d_in[0];
    const float* p    = (const float*)d_in[1];
    const float* bias = (const float*)d_in[2];
    float* out        = (float*)d_out;
    (void)in_sizes; (void)n_in; (void)out_size;

    cudaFuncSetAttribute(prep_P_kernel,
                         cudaFuncAttributeMaxDynamicSharedMemorySize, SMEM_TOTAL);
    cudaFuncSetAttribute(fft_toeplitz_kernel,
                         cudaFuncAttributeMaxDynamicSharedMemorySize, SMEM_TOTAL);

    prep_P_kernel<<<1, NTHREADS, SMEM_TOTAL>>>(p);
    fft_toeplitz_kernel<<<BATCH_SZ / 2, NTHREADS, SMEM_TOTAL>>>(x, bias, out);
}